// round 16
// baseline (speedup 1.0000x reference)
#include <cuda_runtime.h>
#include <cuda_bf16.h>

#define VOCAB 32000
#define EMB   256
#define HID   512
#define BATCH 64
#define SEQ   512

typedef unsigned long long ull;

// ------------------------- device scratch (no runtime alloc) ---------------
__device__ float g_states[(size_t)SEQ * BATCH * HID];  // [s][b][i]
__device__ float g_feat[BATCH * 2 * HID];              // [b][1024]

// ------------------------- packed fp32x2 helpers ---------------------------
__device__ __forceinline__ void fma2(ull& d, ull a, ull b) {
    asm("fma.rn.f32x2 %0, %1, %2, %0;" : "+l"(d) : "l"(a), "l"(b));
}
__device__ __forceinline__ float2 unpack2(ull v) {
    float lo, hi;
    asm("mov.b64 {%0, %1}, %2;" : "=f"(lo), "=f"(hi) : "l"(v));
    return make_float2(lo, hi);
}
__device__ __forceinline__ ull dup2(float x) {
    ull r;
    asm("mov.b64 %0, {%1, %1};" : "=l"(r) : "f"(x));
    return r;
}
__device__ __forceinline__ unsigned smem_u32(const void* p) {
    unsigned a;
    asm("{ .reg .u64 t; cvta.to.shared.u64 t, %1; cvt.u32.u64 %0, t; }"
        : "=r"(a) : "l"(p));
    return a;
}

// ------------------------- no-op spacer kernel -----------------------------
// Stream: H,H,nop,nop,k2,... -> ncu -s 5 -c 1 captures k2_rnn (k1 is gone,
// so add one extra nop to keep k2 at position 6).
__global__ void k0_nop() {}

// ===========================================================================
// K2: persistent clustered RNN + FUSED xin GEMM in the barrier window.
// 16 clusters x 8 CTAs, 512 threads. W_hh in registers (R9 layout).
// W_ih slice (64 rows x 256) in smem; per step, xin(s+1) for this CTA's
// (4 b x 64 i) is computed BETWEEN barrier.cluster.arrive and .wait —
// filling the measured ~70% stall window. h exchange identical to R9.
// ===========================================================================
// dynamic smem layout (bytes):
//   [0      , 16384)  hbuf   float[2][4][512]
//   [16384  , 32768)  red    float[16][256]
//   [32768  , 98304)  wih    ull[128][64]     (k2-pair major, i-local minor)
//   [98304  , 106496) embs   ull[2][4][128]   (parity, batch, k2-pair)
#define K2_SMEM_BYTES 106496

extern __shared__ __align__(16) char k2smem[];

__global__ void __launch_bounds__(512, 1) __cluster_dims__(8, 1, 1)
k2_rnn(const int* __restrict__ X, const float* __restrict__ emb,
       const float* __restrict__ W_ih, const float* __restrict__ W_hh,
       const float* __restrict__ b_ih, const float* __restrict__ b_hh)
{
    float* hbuf = (float*)k2smem;
    float* red  = (float*)(k2smem + 16384);
    ull*   wih  = (ull*)(k2smem + 32768);
    ull*   embs = (ull*)(k2smem + 98304);

    const int t = threadIdx.x;
    unsigned rank;
    asm("mov.u32 %0, %%cluster_ctarank;" : "=r"(rank));
    const int cg = blockIdx.x >> 3;
    const int b0 = cg * 4;

    const int ip   = t & 31;     // W_hh row base (lane)
    const int jseg = t >> 5;     // warp = 32-wide j segment (16 warps)
    const int ob   = t >> 6;     // output batch (valid for t<256)
    const int oi   = t & 63;     // output i (local)
    const int iglob = (int)rank * 64 + oi;

    // ---- W_hh rows in registers: rows (rank*64+ip, +32), j [jseg*32,+32) ----
    ull w0[16], w1[16];
    {
        const ull* wg0 = (const ull*)&W_hh[(size_t)(rank * 64 + ip) * HID + jseg * 32];
        const ull* wg1 = (const ull*)&W_hh[(size_t)(rank * 64 + ip + 32) * HID + jseg * 32];
#pragma unroll
        for (int jj = 0; jj < 16; jj++) { w0[jj] = wg0[jj]; w1[jj] = wg1[jj]; }
    }

    // ---- W_ih slice -> smem, layout wih[k2][i_local] (conflict-free LDS.64) --
    {
        const ull* src = (const ull*)&W_ih[(size_t)(rank * 64) * EMB];
        // src is 64 rows x 128 ull, row-major: src[i*128 + k2]
#pragma unroll
        for (int q = 0; q < 16; q++) {
            int idx = q * 512 + t;          // 0 .. 8191
            int i  = idx >> 7;              // 0..63
            int k2 = idx & 127;             // 0..127
            wih[k2 * 64 + i] = src[(size_t)i * 128 + k2];
        }
    }

    float biasv = 0.f;
    if (t < 256) biasv = b_ih[iglob] + b_hh[iglob];

    // peer base addresses of hbuf (DSMEM)
    unsigned hb32 = smem_u32(hbuf);
    unsigned peer[8];
#pragma unroll
    for (int r = 0; r < 8; r++)
        asm("mapa.shared::cluster.u32 %0, %1, %2;"
            : "=r"(peer[r]) : "r"(hb32), "r"(r));

    __syncthreads();
    asm volatile("barrier.cluster.arrive.aligned;" ::: "memory");
    asm volatile("barrier.cluster.wait.aligned;" ::: "memory");

    // ---- prologue: xin(0) -> xv ----
    float xv = 0.f;
    if (t < 256) {
        int xrow = __ldg(&X[(size_t)(b0 + ob) * SEQ + 0]);
        float4 ev = *(const float4*)&emb[(size_t)xrow * EMB + oi * 4];
        // embs[0][ob][oi*2], [oi*2+1]
        ull* dst = &embs[(size_t)(0 * 4 + ob) * 128 + oi * 2];
        dst[0] = ((const ull*)&ev)[0];
        dst[1] = ((const ull*)&ev)[1];
        asm volatile("bar.sync 1, 256;" ::: "memory");
        ull xacc[4] = {0ull, 0ull, 0ull, 0ull};
        const ull* eb = &embs[(size_t)(0 * 4 + ob) * 128];
#pragma unroll 8
        for (int k2 = 0; k2 < 128; k2 += 4) {
#pragma unroll
            for (int u = 0; u < 4; u++)
                fma2(xacc[u], wih[(k2 + u) * 64 + oi], eb[k2 + u]);
        }
        float2 p0 = unpack2(xacc[0]), p1 = unpack2(xacc[1]);
        float2 p2 = unpack2(xacc[2]), p3 = unpack2(xacc[3]);
        xv = biasv + ((p0.x + p0.y) + (p1.x + p1.y))
                   + ((p2.x + p2.y) + (p3.x + p3.y));
    }

    for (int s = 0; s < SEQ; s++) {
        // prefetch emb row chunk for xin(s+1) (LDG chain hidden behind step)
        float4 ev;
        const bool have = (t < 256) && (s + 1 < SEQ);
        if (have) {
            int xrow = __ldg(&X[(size_t)(b0 + ob) * SEQ + (s + 1)]);
            ev = *(const float4*)&emb[(size_t)xrow * EMB + oi * 4];
        }

        // ---- recurrence: dot = W_hh[iglob] . h(s-1)[b] ----
        float dot = 0.f;
        if (s > 0) {
            const float* hb = hbuf + ((s - 1) & 1) * 2048;
            ull acc[8];
#pragma unroll
            for (int z = 0; z < 8; z++) acc[z] = 0ull;
#pragma unroll
            for (int z = 0; z < 8; z++) {
#pragma unroll
                for (int b = 0; b < 4; b++) {
                    ulonglong2 h2 =
                        *(const ulonglong2*)&hb[b * 512 + jseg * 32 + z * 4];
                    fma2(acc[b],     w0[2 * z],     h2.x);
                    fma2(acc[4 + b], w1[2 * z],     h2.x);
                    fma2(acc[b],     w0[2 * z + 1], h2.y);
                    fma2(acc[4 + b], w1[2 * z + 1], h2.y);
                }
            }
#pragma unroll
            for (int b = 0; b < 4; b++) {
                float2 pa = unpack2(acc[b]);
                float2 pb = unpack2(acc[4 + b]);
                red[jseg * 256 + b * 64 + ip]      = pa.x + pa.y;
                red[jseg * 256 + b * 64 + ip + 32] = pb.x + pb.y;
            }
            __syncthreads();
            if (t < 256) {
                float d0 = 0.f, d1 = 0.f;
#pragma unroll
                for (int z = 0; z < 8; z++) {
                    d0 += red[(2 * z) * 256 + t];
                    d1 += red[(2 * z + 1) * 256 + t];
                }
                dot = d0 + d1;
            }
        }

        // ---- h, pushes ----
        float h = 0.f;
        if (t < 256) {
            h = tanhf(xv + dot);
            if (s < SEQ - 1) {
                unsigned boff = (unsigned)(((s & 1) * 2048 + ob * 512 + iglob) * 4);
#pragma unroll
                for (int r = 0; r < 8; r++)
                    asm volatile("st.shared::cluster.f32 [%0], %1;"
                                 :: "r"(peer[r] + boff), "f"(h) : "memory");
            }
        }
        asm volatile("barrier.cluster.arrive.aligned;" ::: "memory");

        // ======== barrier window: fused xin(s+1) GEMM + g_states store ======
        if (t < 256) {
            g_states[((size_t)s * BATCH + b0 + ob) * HID + iglob] = h;
            if (have) {
                const int pbuf = (s + 1) & 1;
                ull* dst = &embs[(size_t)(pbuf * 4 + ob) * 128 + oi * 2];
                dst[0] = ((const ull*)&ev)[0];
                dst[1] = ((const ull*)&ev)[1];
                asm volatile("bar.sync 1, 256;" ::: "memory");
                ull xacc[4] = {0ull, 0ull, 0ull, 0ull};
                const ull* eb = &embs[(size_t)(pbuf * 4 + ob) * 128];
#pragma unroll 8
                for (int k2 = 0; k2 < 128; k2 += 4) {
#pragma unroll
                    for (int u = 0; u < 4; u++)
                        fma2(xacc[u], wih[(k2 + u) * 64 + oi], eb[k2 + u]);
                }
                float2 p0 = unpack2(xacc[0]), p1 = unpack2(xacc[1]);
                float2 p2 = unpack2(xacc[2]), p3 = unpack2(xacc[3]);
                xv = biasv + ((p0.x + p0.y) + (p1.x + p1.y))
                           + ((p2.x + p2.y) + (p3.x + p3.y));
            }
        }
        // =====================================================================
        asm volatile("barrier.cluster.wait.aligned;" ::: "memory");
    }
}

// ===========================================================================
// K3: attention + feat. One CTA per batch b, 512 threads. (unchanged)
// ===========================================================================
__global__ void __launch_bounds__(512) k3_attn()
{
    __shared__ float lsh[512];
    __shared__ float ash[512];
    __shared__ float red[16];
    const int b = blockIdx.x;
    const int t = threadIdx.x;
    const int lane = t & 31, wid = t >> 5;

    lsh[t] = g_states[((size_t)(SEQ - 1) * BATCH + b) * HID + t];
    __syncthreads();

    for (int s = wid; s < SEQ - 1; s += 16) {
        const float* hs = &g_states[((size_t)s * BATCH + b) * HID];
        float p = 0.f;
#pragma unroll
        for (int m = 0; m < 16; m++)
            p = fmaf(hs[lane + 32 * m], lsh[lane + 32 * m], p);
#pragma unroll
        for (int o = 16; o > 0; o >>= 1) p += __shfl_down_sync(0xffffffffu, p, o);
        if (lane == 0) ash[s] = p;
    }
    __syncthreads();

    float v = (t < SEQ - 1) ? ash[t] : -3.0e38f;
    float mx = v;
#pragma unroll
    for (int o = 16; o > 0; o >>= 1) mx = fmaxf(mx, __shfl_xor_sync(0xffffffffu, mx, o));
    if (lane == 0) red[wid] = mx;
    __syncthreads();
    float m2 = red[0];
#pragma unroll
    for (int i = 1; i < 16; i++) m2 = fmaxf(m2, red[i]);
    __syncthreads();

    float e = (t < SEQ - 1) ? __expf(v - m2) : 0.f;
    float sm = e;
#pragma unroll
    for (int o = 16; o > 0; o >>= 1) sm += __shfl_xor_sync(0xffffffffu, sm, o);
    if (lane == 0) red[wid] = sm;
    __syncthreads();
    float tot = 0.f;
#pragma unroll
    for (int i = 0; i < 16; i++) tot += red[i];
    float inv = 1.f / tot;
    __syncthreads();
    if (t < SEQ - 1) ash[t] = e * inv;
    __syncthreads();

    float ctx = 0.f;
#pragma unroll 4
    for (int s = 0; s < SEQ - 1; s++)
        ctx = fmaf(ash[s], g_states[((size_t)s * BATCH + b) * HID + t], ctx);

    g_feat[b * 1024 + t]       = ctx;
    g_feat[b * 1024 + 512 + t] = lsh[t];
}

// ===========================================================================
// K4: out[b][v] = dot(feat[b], W[v]) + bias[v]. M=64, N=32000, K=1024.
// Tile 64x128 (proven config), double-buffered, grid = 250. (unchanged)
// ===========================================================================
__global__ void __launch_bounds__(256) k4_out(
    const float* __restrict__ W, const float* __restrict__ bias,
    float* __restrict__ out)
{
    __shared__ __align__(16) float As[2][16 * 64];
    __shared__ __align__(16) float Bs[2][16 * 128];
    const int t  = threadIdx.x;
    const int n0 = blockIdx.x * 128;
    const int tx = t & 31, ty = t >> 5;
    const int ml = t >> 2, kq = (t & 3) * 4;
    const int vb = t >> 1, k8 = (t & 1) * 8;

    ull acc2[4][4];
#pragma unroll
    for (int rp = 0; rp < 4; rp++)
#pragma unroll
        for (int c = 0; c < 4; c++) acc2[rp][c] = 0ull;

    const float* aptr = &g_feat[(size_t)ml * 1024 + kq];
    const float* bptr = &W[(size_t)(n0 + vb) * 1024 + k8];

    float4 av  = *(const float4*)&aptr[0];
    float4 bv0 = *(const float4*)&bptr[0];
    float4 bv1 = *(const float4*)&bptr[4];

    for (int it = 0; it < 64; it++) {
        const int buf = it & 1;
        As[buf][(kq + 0) * 64 + ml] = av.x;
        As[buf][(kq + 1) * 64 + ml] = av.y;
        As[buf][(kq + 2) * 64 + ml] = av.z;
        As[buf][(kq + 3) * 64 + ml] = av.w;
        Bs[buf][(k8 + 0) * 128 + vb] = bv0.x;
        Bs[buf][(k8 + 1) * 128 + vb] = bv0.y;
        Bs[buf][(k8 + 2) * 128 + vb] = bv0.z;
        Bs[buf][(k8 + 3) * 128 + vb] = bv0.w;
        Bs[buf][(k8 + 4) * 128 + vb] = bv1.x;
        Bs[buf][(k8 + 5) * 128 + vb] = bv1.y;
        Bs[buf][(k8 + 6) * 128 + vb] = bv1.z;
        Bs[buf][(k8 + 7) * 128 + vb] = bv1.w;
        __syncthreads();
        if (it < 63) {
            const int k0 = (it + 1) * 16;
            av  = *(const float4*)&aptr[k0];
            bv0 = *(const float4*)&bptr[k0];
            bv1 = *(const float4*)&bptr[k0 + 4];
        }
#pragma unroll
        for (int kk = 0; kk < 16; kk++) {
            const ull* ap = (const ull*)&As[buf][kk * 64 + ty * 8];
            ull a0 = ap[0], a1 = ap[1], a2 = ap[2], a3 = ap[3];
            float4 Wv = *(const float4*)&Bs[buf][kk * 128 + tx * 4];
            ull wd[4] = {dup2(Wv.x), dup2(Wv.y), dup2(Wv.z), dup2(Wv.w)};
#pragma unroll
            for (int c = 0; c < 4; c++) {
                fma2(acc2[0][c], a0, wd[c]);
                fma2(acc2[1][c], a1, wd[c]);
                fma2(acc2[2][c], a2, wd[c]);
                fma2(acc2[3][c], a3, wd[c]);
            }
        }
    }

    const int nbase = n0 + tx * 4;
    float bv_0 = bias[nbase + 0], bv_1 = bias[nbase + 1];
    float bv_2 = bias[nbase + 2], bv_3 = bias[nbase + 3];
#pragma unroll
    for (int rp = 0; rp < 4; rp++) {
        float2 p0 = unpack2(acc2[rp][0]);
        float2 p1 = unpack2(acc2[rp][1]);
        float2 p2 = unpack2(acc2[rp][2]);
        float2 p3 = unpack2(acc2[rp][3]);
        int bb0 = ty * 8 + 2 * rp;
        float4 o0, o1;
        o0.x = p0.x + bv_0; o0.y = p1.x + bv_1; o0.z = p2.x + bv_2; o0.w = p3.x + bv_3;
        o1.x = p0.y + bv_0; o1.y = p1.y + bv_1; o1.z = p2.y + bv_2; o1.w = p3.y + bv_3;
        *(float4*)&out[(size_t)bb0 * VOCAB + nbase]       = o0;
        *(float4*)&out[(size_t)(bb0 + 1) * VOCAB + nbase] = o1;
    }
}

// ===========================================================================
extern "C" void kernel_launch(void* const* d_in, const int* in_sizes, int n_in,
                              void* d_out, int out_size) {
    (void)in_sizes; (void)n_in; (void)out_size;
    const int*   X    = (const int*)d_in[0];
    const float* emb  = (const float*)d_in[1];
    const float* W_ih = (const float*)d_in[2];
    const float* W_hh = (const float*)d_in[3];
    const float* b_ih = (const float*)d_in[4];
    const float* b_hh = (const float*)d_in[5];
    const float* W    = (const float*)d_in[6];
    const float* bias = (const float*)d_in[7];
    float* out = (float*)d_out;

    // 3 spacers: k1 is fused away, so stream = H,H,nop,nop,nop,[k2] at -s 5.
    k0_nop<<<1, 32>>>();
    k0_nop<<<1, 32>>>();
    k0_nop<<<1, 32>>>();

    cudaFuncSetAttribute(k2_rnn, cudaFuncAttributeMaxDynamicSharedMemorySize,
                         K2_SMEM_BYTES);
    k2_rnn<<<128, 512, K2_SMEM_BYTES>>>(X, emb, W_ih, W_hh, b_ih, b_hh);
    k3_attn<<<BATCH, 512>>>();
    k4_out<<<VOCAB / 128, 256>>>(W, bias, out);
}

// round 17
// speedup vs baseline: 1.4915x; 1.4915x over previous
#include <cuda_runtime.h>
#include <cuda_bf16.h>

#define VOCAB 32000
#define EMB   256
#define HID   512
#define BATCH 64
#define SEQ   512
#define NB_RNN 256   // 256 CTAs, 2 per SM

typedef unsigned long long ull;

// ------------------------- device scratch (no runtime alloc) ---------------
__device__ float g_xin[(size_t)SEQ * BATCH * HID];     // [s][b][i]
__device__ float g_states[(size_t)SEQ * BATCH * HID];  // [s][b][i]
__device__ float g_feat[BATCH * 2 * HID];              // [b][1024]
__device__ unsigned int g_bar_count;                   // zero-init
__device__ unsigned int g_bar_gen;                     // zero-init

// ------------------------- packed fp32x2 helpers ---------------------------
__device__ __forceinline__ void fma2(ull& d, ull a, ull b) {
    asm("fma.rn.f32x2 %0, %1, %2, %0;" : "+l"(d) : "l"(a), "l"(b));
}
__device__ __forceinline__ float2 unpack2(ull v) {
    float lo, hi;
    asm("mov.b64 {%0, %1}, %2;" : "=f"(lo), "=f"(hi) : "l"(v));
    return make_float2(lo, hi);
}
__device__ __forceinline__ ull dup2(float x) {
    ull r;
    asm("mov.b64 %0, {%1, %1};" : "=l"(r) : "f"(x));
    return r;
}

// ------------------------- grid barrier (256 co-resident CTAs) -------------
__device__ __forceinline__ void grid_barrier_256() {
    __syncthreads();
    if (threadIdx.x == 0) {
        unsigned int g;
        asm volatile("ld.acquire.gpu.u32 %0, [%1];"
                     : "=r"(g) : "l"(&g_bar_gen) : "memory");
        __threadfence();
        unsigned int arrived = atomicAdd(&g_bar_count, 1u);
        if (arrived == NB_RNN - 1) {
            atomicExch(&g_bar_count, 0u);
            unsigned int ng = g + 1u;
            asm volatile("st.release.gpu.u32 [%0], %1;"
                         :: "l"(&g_bar_gen), "r"(ng) : "memory");
        } else {
            unsigned int cur;
            do {
                asm volatile("ld.acquire.gpu.u32 %0, [%1];"
                             : "=r"(cur) : "l"(&g_bar_gen) : "memory");
            } while (cur == g);
        }
    }
    __syncthreads();
}

// ------------------------- no-op spacer kernel -----------------------------
// Stream: H,H,nop,nop,k1,[k2] -> ncu -s 5 -c 1 captures k2_rnn.
__global__ void k0_nop() {}

// ===========================================================================
// K1: xin[s][b][i] = dot(emb[X[b,s]], W_ih[i]) + b_ih[i] + b_hh[i]
// GEMM M=32768 (m = s*64+b), N=512, K=256. Tile 64x128, double-buffered.
// (R9 proven, unchanged)
// ===========================================================================
__global__ void __launch_bounds__(256) k1_xin(
    const int* __restrict__ X, const float* __restrict__ emb,
    const float* __restrict__ W_ih, const float* __restrict__ b_ih,
    const float* __restrict__ b_hh)
{
    __shared__ int rsh[64];
    __shared__ __align__(16) float As[2][16 * 64];   // [buf][k][m]
    __shared__ __align__(16) float Bs[2][16 * 128];  // [buf][k][n]
    const int t  = threadIdx.x;
    const int mt = blockIdx.x;            // == s
    const int n0 = blockIdx.y * 128;
    if (t < 64) rsh[t] = X[(size_t)t * SEQ + mt];

    const int tx = t & 31, ty = t >> 5;
    const int ml = t >> 2, kq = (t & 3) * 4;
    const int vb = t >> 1, k8 = (t & 1) * 8;

    ull acc2[4][4];
#pragma unroll
    for (int rp = 0; rp < 4; rp++)
#pragma unroll
        for (int c = 0; c < 4; c++) acc2[rp][c] = 0ull;

    __syncthreads();
    const int arow = rsh[ml];
    const float* aptr = &emb[(size_t)arow * EMB + kq];
    const float* bptr = &W_ih[(size_t)(n0 + vb) * EMB + k8];

    float4 av  = *(const float4*)&aptr[0];
    float4 bv0 = *(const float4*)&bptr[0];
    float4 bv1 = *(const float4*)&bptr[4];

    for (int it = 0; it < 16; it++) {
        const int buf = it & 1;
        As[buf][(kq + 0) * 64 + ml] = av.x;
        As[buf][(kq + 1) * 64 + ml] = av.y;
        As[buf][(kq + 2) * 64 + ml] = av.z;
        As[buf][(kq + 3) * 64 + ml] = av.w;
        Bs[buf][(k8 + 0) * 128 + vb] = bv0.x;
        Bs[buf][(k8 + 1) * 128 + vb] = bv0.y;
        Bs[buf][(k8 + 2) * 128 + vb] = bv0.z;
        Bs[buf][(k8 + 3) * 128 + vb] = bv0.w;
        Bs[buf][(k8 + 4) * 128 + vb] = bv1.x;
        Bs[buf][(k8 + 5) * 128 + vb] = bv1.y;
        Bs[buf][(k8 + 6) * 128 + vb] = bv1.z;
        Bs[buf][(k8 + 7) * 128 + vb] = bv1.w;
        __syncthreads();
        if (it < 15) {
            const int k0 = (it + 1) * 16;
            av  = *(const float4*)&aptr[k0];
            bv0 = *(const float4*)&bptr[k0];
            bv1 = *(const float4*)&bptr[k0 + 4];
        }
#pragma unroll
        for (int kk = 0; kk < 16; kk++) {
            const ull* ap = (const ull*)&As[buf][kk * 64 + ty * 8];
            ull a0 = ap[0], a1 = ap[1], a2 = ap[2], a3 = ap[3];
            float4 Wv = *(const float4*)&Bs[buf][kk * 128 + tx * 4];
            ull wd[4] = {dup2(Wv.x), dup2(Wv.y), dup2(Wv.z), dup2(Wv.w)};
#pragma unroll
            for (int c = 0; c < 4; c++) {
                fma2(acc2[0][c], a0, wd[c]);
                fma2(acc2[1][c], a1, wd[c]);
                fma2(acc2[2][c], a2, wd[c]);
                fma2(acc2[3][c], a3, wd[c]);
            }
        }
    }

    const int nbase = n0 + tx * 4;
    float bias[4];
#pragma unroll
    for (int c = 0; c < 4; c++) bias[c] = b_ih[nbase + c] + b_hh[nbase + c];
#pragma unroll
    for (int rp = 0; rp < 4; rp++) {
        float2 p0 = unpack2(acc2[rp][0]);
        float2 p1 = unpack2(acc2[rp][1]);
        float2 p2 = unpack2(acc2[rp][2]);
        float2 p3 = unpack2(acc2[rp][3]);
        int bl0 = ty * 8 + 2 * rp;
        float4 o0, o1;
        o0.x = p0.x + bias[0]; o0.y = p1.x + bias[1];
        o0.z = p2.x + bias[2]; o0.w = p3.x + bias[3];
        o1.x = p0.y + bias[0]; o1.y = p1.y + bias[1];
        o1.z = p2.y + bias[2]; o1.w = p3.y + bias[3];
        *(float4*)&g_xin[((size_t)mt * BATCH + bl0) * HID + nbase]     = o0;
        *(float4*)&g_xin[((size_t)mt * BATCH + bl0 + 1) * HID + nbase] = o1;
    }
}

// ===========================================================================
// K2: persistent RNN, 256 CTAs x 256 threads, TWO CTAs PER SM.
// CTA (ig = bid&15, bg = bid>>4): i-rows [ig*32,+32), batches [bg*4,+4).
// W_hh rows in registers: lane -> row ig*32+lane, warp w (8) -> j [w*64,+64)
// = 32 ull/thread. h exchange through L2 (g_states, unique addr per step,
// R12-proven); R5-proven sense-reversing atomic grid barrier (count 256).
// The 2 co-resident CTAs interleave each other's exposed latencies.
// ===========================================================================
__global__ void __launch_bounds__(256, 2) k2_rnn(const float* __restrict__ W_hh)
{
    __shared__ __align__(16) float hbuf[4 * 512];   // staged h(s-1) [b][j]
    __shared__ float red[8 * 128];                  // [w][b*32+i]

    const int t    = threadIdx.x;
    const int lane = t & 31;
    const int w    = t >> 5;                 // j-seg (8 warps x 64 j)
    const int ig   = blockIdx.x & 15;
    const int bg   = blockIdx.x >> 4;
    const int b0   = bg * 4;

    // output role (threads 0..127): b_o = t>>5, i_o = t&31
    const int bo = t >> 5;
    const int io = t & 31;

    // ---- W_hh row in registers: row ig*32+lane, j [w*64, w*64+64) ----
    ull wreg[32];
    {
        const ull* wg = (const ull*)&W_hh[(size_t)(ig * 32 + lane) * HID + w * 64];
#pragma unroll
        for (int jj = 0; jj < 32; jj++) wreg[jj] = wg[jj];
    }

    for (int s = 0; s < SEQ; s++) {
        float dot = 0.f;
        if (s > 0) {
            // stage h(s-1) for this CTA's 4 batches: 8 KB, fully coalesced
            const float4* src = (const float4*)
                &g_states[((size_t)(s - 1) * BATCH + b0) * HID];
            float4* dst = (float4*)hbuf;
            dst[t]       = src[t];
            dst[t + 256] = src[t + 256];
            __syncthreads();

            ull acc[4];
#pragma unroll
            for (int b = 0; b < 4; b++) acc[b] = 0ull;
#pragma unroll
            for (int z = 0; z < 16; z++) {
#pragma unroll
                for (int b = 0; b < 4; b++) {
                    // broadcast LDS.128: h[b][w*64 + 4z .. +3]
                    ulonglong2 h2 =
                        *(const ulonglong2*)&hbuf[b * 512 + w * 64 + z * 4];
                    fma2(acc[b], wreg[2 * z],     h2.x);
                    fma2(acc[b], wreg[2 * z + 1], h2.y);
                }
            }
#pragma unroll
            for (int b = 0; b < 4; b++) {
                float2 p = unpack2(acc[b]);
                red[w * 128 + b * 32 + lane] = p.x + p.y;
            }
            __syncthreads();
            if (t < 128) {
                float d0 = 0.f, d1 = 0.f;
#pragma unroll
                for (int z = 0; z < 4; z++) {
                    d0 += red[(2 * z) * 128 + t];
                    d1 += red[(2 * z + 1) * 128 + t];
                }
                dot = d0 + d1;
            }
        }

        if (t < 128) {
            float xv = __ldg(&g_xin[((size_t)s * BATCH + b0 + bo) * HID
                                    + ig * 32 + io]);
            float h = tanhf(xv + dot);
            g_states[((size_t)s * BATCH + b0 + bo) * HID + ig * 32 + io] = h;
        }
        grid_barrier_256();   // h(s) globally visible
    }
}

// ===========================================================================
// K3: attention + feat. One CTA per batch b, 512 threads. (unchanged)
// ===========================================================================
__global__ void __launch_bounds__(512) k3_attn()
{
    __shared__ float lsh[512];
    __shared__ float ash[512];
    __shared__ float red[16];
    const int b = blockIdx.x;
    const int t = threadIdx.x;
    const int lane = t & 31, wid = t >> 5;

    lsh[t] = g_states[((size_t)(SEQ - 1) * BATCH + b) * HID + t];
    __syncthreads();

    for (int s = wid; s < SEQ - 1; s += 16) {
        const float* hs = &g_states[((size_t)s * BATCH + b) * HID];
        float p = 0.f;
#pragma unroll
        for (int m = 0; m < 16; m++)
            p = fmaf(hs[lane + 32 * m], lsh[lane + 32 * m], p);
#pragma unroll
        for (int o = 16; o > 0; o >>= 1) p += __shfl_down_sync(0xffffffffu, p, o);
        if (lane == 0) ash[s] = p;
    }
    __syncthreads();

    float v = (t < SEQ - 1) ? ash[t] : -3.0e38f;
    float mx = v;
#pragma unroll
    for (int o = 16; o > 0; o >>= 1) mx = fmaxf(mx, __shfl_xor_sync(0xffffffffu, mx, o));
    if (lane == 0) red[wid] = mx;
    __syncthreads();
    float m2 = red[0];
#pragma unroll
    for (int i = 1; i < 16; i++) m2 = fmaxf(m2, red[i]);
    __syncthreads();

    float e = (t < SEQ - 1) ? __expf(v - m2) : 0.f;
    float sm = e;
#pragma unroll
    for (int o = 16; o > 0; o >>= 1) sm += __shfl_xor_sync(0xffffffffu, sm, o);
    if (lane == 0) red[wid] = sm;
    __syncthreads();
    float tot = 0.f;
#pragma unroll
    for (int i = 0; i < 16; i++) tot += red[i];
    float inv = 1.f / tot;
    __syncthreads();
    if (t < SEQ - 1) ash[t] = e * inv;
    __syncthreads();

    float ctx = 0.f;
#pragma unroll 4
    for (int s = 0; s < SEQ - 1; s++)
        ctx = fmaf(ash[s], g_states[((size_t)s * BATCH + b) * HID + t], ctx);

    g_feat[b * 1024 + t]       = ctx;
    g_feat[b * 1024 + 512 + t] = lsh[t];
}

// ===========================================================================
// K4: out[b][v] = dot(feat[b], W[v]) + bias[v]. M=64, N=32000, K=1024.
// Tile 64x128 (proven config), double-buffered, grid = 250. (unchanged)
// ===========================================================================
__global__ void __launch_bounds__(256) k4_out(
    const float* __restrict__ W, const float* __restrict__ bias,
    float* __restrict__ out)
{
    __shared__ __align__(16) float As[2][16 * 64];
    __shared__ __align__(16) float Bs[2][16 * 128];
    const int t  = threadIdx.x;
    const int n0 = blockIdx.x * 128;
    const int tx = t & 31, ty = t >> 5;
    const int ml = t >> 2, kq = (t & 3) * 4;
    const int vb = t >> 1, k8 = (t & 1) * 8;

    ull acc2[4][4];
#pragma unroll
    for (int rp = 0; rp < 4; rp++)
#pragma unroll
        for (int c = 0; c < 4; c++) acc2[rp][c] = 0ull;

    const float* aptr = &g_feat[(size_t)ml * 1024 + kq];
    const float* bptr = &W[(size_t)(n0 + vb) * 1024 + k8];

    float4 av  = *(const float4*)&aptr[0];
    float4 bv0 = *(const float4*)&bptr[0];
    float4 bv1 = *(const float4*)&bptr[4];

    for (int it = 0; it < 64; it++) {
        const int buf = it & 1;
        As[buf][(kq + 0) * 64 + ml] = av.x;
        As[buf][(kq + 1) * 64 + ml] = av.y;
        As[buf][(kq + 2) * 64 + ml] = av.z;
        As[buf][(kq + 3) * 64 + ml] = av.w;
        Bs[buf][(k8 + 0) * 128 + vb] = bv0.x;
        Bs[buf][(k8 + 1) * 128 + vb] = bv0.y;
        Bs[buf][(k8 + 2) * 128 + vb] = bv0.z;
        Bs[buf][(k8 + 3) * 128 + vb] = bv0.w;
        Bs[buf][(k8 + 4) * 128 + vb] = bv1.x;
        Bs[buf][(k8 + 5) * 128 + vb] = bv1.y;
        Bs[buf][(k8 + 6) * 128 + vb] = bv1.z;
        Bs[buf][(k8 + 7) * 128 + vb] = bv1.w;
        __syncthreads();
        if (it < 63) {
            const int k0 = (it + 1) * 16;
            av  = *(const float4*)&aptr[k0];
            bv0 = *(const float4*)&bptr[k0];
            bv1 = *(const float4*)&bptr[k0 + 4];
        }
#pragma unroll
        for (int kk = 0; kk < 16; kk++) {
            const ull* ap = (const ull*)&As[buf][kk * 64 + ty * 8];
            ull a0 = ap[0], a1 = ap[1], a2 = ap[2], a3 = ap[3];
            float4 Wv = *(const float4*)&Bs[buf][kk * 128 + tx * 4];
            ull wd[4] = {dup2(Wv.x), dup2(Wv.y), dup2(Wv.z), dup2(Wv.w)};
#pragma unroll
            for (int c = 0; c < 4; c++) {
                fma2(acc2[0][c], a0, wd[c]);
                fma2(acc2[1][c], a1, wd[c]);
                fma2(acc2[2][c], a2, wd[c]);
                fma2(acc2[3][c], a3, wd[c]);
            }
        }
    }

    const int nbase = n0 + tx * 4;
    float bv_0 = bias[nbase + 0], bv_1 = bias[nbase + 1];
    float bv_2 = bias[nbase + 2], bv_3 = bias[nbase + 3];
#pragma unroll
    for (int rp = 0; rp < 4; rp++) {
        float2 p0 = unpack2(acc2[rp][0]);
        float2 p1 = unpack2(acc2[rp][1]);
        float2 p2 = unpack2(acc2[rp][2]);
        float2 p3 = unpack2(acc2[rp][3]);
        int bb0 = ty * 8 + 2 * rp;
        float4 o0, o1;
        o0.x = p0.x + bv_0; o0.y = p1.x + bv_1; o0.z = p2.x + bv_2; o0.w = p3.x + bv_3;
        o1.x = p0.y + bv_0; o1.y = p1.y + bv_1; o1.z = p2.y + bv_2; o1.w = p3.y + bv_3;
        *(float4*)&out[(size_t)bb0 * VOCAB + nbase]       = o0;
        *(float4*)&out[(size_t)(bb0 + 1) * VOCAB + nbase] = o1;
    }
}

// ===========================================================================
extern "C" void kernel_launch(void* const* d_in, const int* in_sizes, int n_in,
                              void* d_out, int out_size) {
    (void)in_sizes; (void)n_in; (void)out_size;
    const int*   X    = (const int*)d_in[0];
    const float* emb  = (const float*)d_in[1];
    const float* W_ih = (const float*)d_in[2];
    const float* W_hh = (const float*)d_in[3];
    const float* b_ih = (const float*)d_in[4];
    const float* b_hh = (const float*)d_in[5];
    const float* W    = (const float*)d_in[6];
    const float* bias = (const float*)d_in[7];
    float* out = (float*)d_out;

    // 2 spacers: stream = H,H,nop,nop,k1,[k2] -> ncu -s 5 -c 1 captures k2.
    k0_nop<<<1, 32>>>();
    k0_nop<<<1, 32>>>();

    k1_xin<<<dim3(SEQ, 4), 256>>>(X, emb, W_ih, b_ih, b_hh);
    k2_rnn<<<NB_RNN, 256>>>(W_hh);
    k3_attn<<<BATCH, 512>>>();
    k4_out<<<VOCAB / 128, 256>>>(W, bias, out);
}